// round 2
// baseline (speedup 1.0000x reference)
#include <cuda_runtime.h>
#include <cuda_bf16.h>
#include <math_constants.h>
#include <cstdint>

// Problem constants (fixed by dataset)
#define NN     50000
#define EE     800000
#define GG     512
#define IN_DIM 16
#define EDGE_DIM 8
#define HIDC   32
#define OUTD   64
#define HEADS  4
#define D2     (HEADS*HIDC)   // 128

#define SCAN_BLK 1024
#define SCAN_NB  ((NN + SCAN_BLK - 1) / SCAN_BLK)   // 49

// ---------------- device scratch (no runtime allocation allowed) ----------------
__device__ float g_xs[NN * D2];
__device__ float g_xd[NN * D2];
__device__ float g_h1[NN * D2];
__device__ float g_h2[NN * D2];
__device__ float g_h3[NN * HIDC];
__device__ float g_escore[EE * HEADS];
__device__ float g_attr_p[EE * EDGE_DIM];
__device__ int   g_deg[NN];
__device__ int   g_tmp[SCAN_NB * SCAN_BLK];
__device__ int   g_rowptr[NN + 1];
__device__ int   g_wp[NN];
__device__ int   g_blksum[SCAN_NB + 1];
__device__ int2  g_csr[EE];     // (src, eid) per csr slot
__device__ int   g_dstn[EE];    // dst per csr slot
__device__ float g_sums[GG * HIDC];
__device__ float g_cnt[GG];

// ---------------- CSR build ----------------
__global__ void zero_kernel() {
    int i = blockIdx.x * blockDim.x + threadIdx.x;
    if (i < NN) g_deg[i] = 0;
    if (i < GG * HIDC) g_sums[i] = 0.f;
    if (i < GG) g_cnt[i] = 0.f;
}

__global__ void hist_kernel(const int* __restrict__ dst) {
    int e = blockIdx.x * blockDim.x + threadIdx.x;
    if (e < EE) atomicAdd(&g_deg[dst[e]], 1);
}

__global__ void scan1_kernel() {
    __shared__ int sm[SCAN_BLK];
    int tid = threadIdx.x;
    int i = blockIdx.x * SCAN_BLK + tid;
    int v = (i < NN) ? g_deg[i] : 0;
    sm[tid] = v;
    __syncthreads();
    for (int o = 1; o < SCAN_BLK; o <<= 1) {
        int t = (tid >= o) ? sm[tid - o] : 0;
        __syncthreads();
        sm[tid] += t;
        __syncthreads();
    }
    g_tmp[blockIdx.x * SCAN_BLK + tid] = sm[tid] - v;   // exclusive within block
    if (tid == SCAN_BLK - 1) g_blksum[blockIdx.x] = sm[tid];
}

__global__ void scan2_kernel() {
    if (threadIdx.x == 0 && blockIdx.x == 0) {
        int run = 0;
        for (int b = 0; b < SCAN_NB; b++) {
            int t = g_blksum[b];
            g_blksum[b] = run;
            run += t;
        }
    }
}

__global__ void scan3_kernel() {
    int i = blockIdx.x * blockDim.x + threadIdx.x;
    if (i < NN) {
        int v = g_tmp[i] + g_blksum[i / SCAN_BLK];
        g_rowptr[i] = v;
        g_wp[i] = v;
    }
    if (i == 0) g_rowptr[NN] = EE;
}

__global__ void scatter_kernel(const int* __restrict__ src, const int* __restrict__ dst) {
    int e = blockIdx.x * blockDim.x + threadIdx.x;
    if (e < EE) {
        int d = dst[e];
        int pos = atomicAdd(&g_wp[d], 1);
        g_csr[pos] = make_int2(src[e], e);
        g_dstn[pos] = d;
    }
}

// permute edge_attr into csr order (reused by all 3 layers)
__global__ void permute_attr_kernel(const float* __restrict__ edge_attr) {
    int idx = blockIdx.x * blockDim.x + threadIdx.x;
    if (idx >= EE) return;
    int eid = g_csr[idx].y;
    const float4* ap = reinterpret_cast<const float4*>(edge_attr + (size_t)eid * EDGE_DIM);
    float4 a0 = __ldg(ap), a1 = __ldg(ap + 1);
    float4* op = reinterpret_cast<float4*>(g_attr_p + (size_t)idx * EDGE_DIM);
    op[0] = a0; op[1] = a1;
}

// ---------------- node linear (packed f32x2): xs = x@Ws+bs, xd = x@Wd+bd ----------------
// block = DOUT threads, each block handles TN nodes (TN even; NN % TN == 0).
template<int DIN, int DOUT, int TN>
__global__ void node_linear_kernel(const float* __restrict__ x,
                                   const float* __restrict__ Ws, const float* __restrict__ Wd,
                                   const float* __restrict__ bs, const float* __restrict__ bd,
                                   float* __restrict__ xs, float* __restrict__ xd) {
    __shared__ float xsm[DIN][TN];       // transposed: [k][node]
    const int n0 = blockIdx.x * TN;
    const int tid = threadIdx.x;
    for (int i = tid; i < TN * DIN; i += DOUT) {
        int t = i / DIN, k = i % DIN;
        xsm[k][t] = x[(size_t)(n0 + t) * DIN + k];
    }
    __syncthreads();

    unsigned long long accs[TN / 2], accd[TN / 2];
#pragma unroll
    for (int p = 0; p < TN / 2; p++) { accs[p] = 0ull; accd[p] = 0ull; }

#pragma unroll 4
    for (int k = 0; k < DIN; k++) {
        float wsv = __ldg(Ws + k * DOUT + tid);
        float wdv = __ldg(Wd + k * DOUT + tid);
        unsigned long long ws2, wd2;
        asm("mov.b64 %0, {%1, %2};" : "=l"(ws2) : "f"(wsv), "f"(wsv));
        asm("mov.b64 %0, {%1, %2};" : "=l"(wd2) : "f"(wdv), "f"(wdv));
        const unsigned long long* xp = reinterpret_cast<const unsigned long long*>(&xsm[k][0]);
#pragma unroll
        for (int p = 0; p < TN / 2; p++) {
            unsigned long long xv = xp[p];
            asm("fma.rn.f32x2 %0, %1, %2, %3;" : "=l"(accs[p]) : "l"(xv), "l"(ws2), "l"(accs[p]));
            asm("fma.rn.f32x2 %0, %1, %2, %3;" : "=l"(accd[p]) : "l"(xv), "l"(wd2), "l"(accd[p]));
        }
    }
    float bsv = __ldg(bs + tid), bdv = __ldg(bd + tid);
#pragma unroll
    for (int p = 0; p < TN / 2; p++) {
        float s_lo, s_hi, d_lo, d_hi;
        asm("mov.b64 {%0, %1}, %2;" : "=f"(s_lo), "=f"(s_hi) : "l"(accs[p]));
        asm("mov.b64 {%0, %1}, %2;" : "=f"(d_lo), "=f"(d_hi) : "l"(accd[p]));
        int n = n0 + 2 * p;
        xs[(size_t)n * DOUT + tid] = s_lo + bsv;
        xs[(size_t)(n + 1) * DOUT + tid] = s_hi + bsv;
        xd[(size_t)n * DOUT + tid] = d_lo + bdv;
        xd[(size_t)(n + 1) * DOUT + tid] = d_hi + bdv;
    }
}

// ---------------- GATv2 scores: thread per (csr slot, head) ----------------
template<int H, int TPB>
__global__ void gat_score_kernel(const float* __restrict__ xs, const float* __restrict__ xd,
                                 const float* __restrict__ We, const float* __restrict__ att,
                                 float* __restrict__ escore) {
    const int HC = H * 32;
    __shared__ float Wet[32 * H * 8];   // row = c*H + h (head-interleaved), 8 k's per row
    __shared__ float att_s[32 * H];     // [c*H + h]
    for (int i = threadIdx.x; i < HC * 8; i += TPB) {
        int col = i >> 3, k = i & 7;
        int c = col & 31, h = col >> 5;
        Wet[(c * H + h) * 8 + k] = We[k * HC + col];
    }
    for (int i = threadIdx.x; i < HC; i += TPB) {
        int c = i & 31, h = i >> 5;
        att_s[c * H + h] = att[i];
    }
    __syncthreads();

    int t = blockIdx.x * TPB + threadIdx.x;
    if (t >= EE * H) return;
    int idx = t / H;
    int h = t - idx * H;

    int src = g_csr[idx].x;
    int dst = g_dstn[idx];
    const float4* ap = reinterpret_cast<const float4*>(g_attr_p + (size_t)idx * EDGE_DIM);
    float4 a0 = ap[0], a1 = ap[1];
    float attr[8] = {a0.x, a0.y, a0.z, a0.w, a1.x, a1.y, a1.z, a1.w};

    const float4* xsp = reinterpret_cast<const float4*>(xs + (size_t)src * HC + h * 32);
    const float4* xdp = reinterpret_cast<const float4*>(xd + (size_t)dst * HC + h * 32);

    float e = 0.f;
#pragma unroll
    for (int c4 = 0; c4 < 8; c4++) {
        float4 xsv = __ldg(xsp + c4);
        float4 xdv = __ldg(xdp + c4);
        const float* xsa = &xsv.x;
        const float* xda = &xdv.x;
#pragma unroll
        for (int q = 0; q < 4; q++) {
            int c = c4 * 4 + q;
            const float4* wr = reinterpret_cast<const float4*>(&Wet[(c * H + h) * 8]);
            float4 w0 = wr[0], w1 = wr[1];
            float z = xsa[q] + xda[q]
                    + attr[0] * w0.x + attr[1] * w0.y + attr[2] * w0.z + attr[3] * w0.w
                    + attr[4] * w1.x + attr[5] * w1.y + attr[6] * w1.z + attr[7] * w1.w;
            z = (z > 0.f) ? z : 0.2f * z;
            e += z * att_s[c * H + h];
        }
    }
    escore[(size_t)idx * H + h] = e;
}

// score loader (float4 when H==4)
template<int H>
__device__ __forceinline__ void load_scores(const float* __restrict__ escore, int i, float* e) {
    if (H == 4) {
        float4 v = __ldg(reinterpret_cast<const float4*>(escore + (size_t)i * 4));
        e[0] = v.x; e[1] = v.y; e[2] = v.z; e[3] = v.w;
    } else {
        e[0] = __ldg(escore + i);
    }
}

// ---------------- softmax + aggregate: warp per node, heads fused ----------------
template<int H, bool ELU>
__global__ void gat_aggregate_kernel(const float* __restrict__ xs,
                                     const float* __restrict__ escore,
                                     const float* __restrict__ bias,
                                     float* __restrict__ out) {
    const int HC = H * 32;
    __shared__ float s_al[8][32 * H];
    __shared__ int   s_src[8][32];
    int wq = threadIdx.x >> 5;
    int lane = threadIdx.x & 31;
    int n = (blockIdx.x * blockDim.x + threadIdx.x) >> 5;
    if (n >= NN) return;
    int s0 = __ldg(&g_rowptr[n]), s1 = __ldg(&g_rowptr[n + 1]);

    float bv[H];
#pragma unroll
    for (int h = 0; h < H; h++) bv[h] = __ldg(bias + h * 32 + lane);

    if (s0 == s1) {
#pragma unroll
        for (int h = 0; h < H; h++) {
            float o = bv[h];
            if (ELU) o = (o > 0.f) ? o : expm1f(o);
            out[(size_t)n * HC + h * 32 + lane] = o;
        }
        return;
    }

    // pass 1a: per-head max
    float m[H];
#pragma unroll
    for (int h = 0; h < H; h++) m[h] = -CUDART_INF_F;
    for (int base = s0; base < s1; base += 32) {
        int i = base + lane;
        if (i < s1) {
            float e[H];
            load_scores<H>(escore, i, e);
#pragma unroll
            for (int h = 0; h < H; h++) m[h] = fmaxf(m[h], e[h]);
        }
    }
#pragma unroll
    for (int h = 0; h < H; h++)
#pragma unroll
        for (int o = 16; o > 0; o >>= 1) m[h] = fmaxf(m[h], __shfl_xor_sync(0xffffffffu, m[h], o));

    // pass 1b: per-head sum of exp
    float sum[H];
#pragma unroll
    for (int h = 0; h < H; h++) sum[h] = 0.f;
    for (int base = s0; base < s1; base += 32) {
        int i = base + lane;
        if (i < s1) {
            float e[H];
            load_scores<H>(escore, i, e);
#pragma unroll
            for (int h = 0; h < H; h++) sum[h] += __expf(e[h] - m[h]);
        }
    }
#pragma unroll
    for (int h = 0; h < H; h++)
#pragma unroll
        for (int o = 16; o > 0; o >>= 1) sum[h] += __shfl_xor_sync(0xffffffffu, sum[h], o);
    float inv[H];
#pragma unroll
    for (int h = 0; h < H; h++) inv[h] = 1.f / sum[h];

    // pass 2: aggregate
    float acc[H];
#pragma unroll
    for (int h = 0; h < H; h++) acc[h] = 0.f;
    for (int base = s0; base < s1; base += 32) {
        int i = base + lane;
        int c = s1 - base; if (c > 32) c = 32;
        if (i < s1) {
            float e[H];
            load_scores<H>(escore, i, e);
#pragma unroll
            for (int h = 0; h < H; h++) s_al[wq][lane * H + h] = __expf(e[h] - m[h]) * inv[h];
            s_src[wq][lane] = g_csr[i].x;
        }
        __syncwarp();
        for (int j = 0; j < c; j++) {
            int sj = s_src[wq][j];
            if (H == 4) {
                float4 a = *reinterpret_cast<const float4*>(&s_al[wq][j * 4]);
                const float* xp = xs + (size_t)sj * 128;
                acc[0] += a.x * __ldg(xp + lane);
                acc[1] += a.y * __ldg(xp + 32 + lane);
                acc[2] += a.z * __ldg(xp + 64 + lane);
                acc[3] += a.w * __ldg(xp + 96 + lane);
            } else {
                float a = s_al[wq][j];
                acc[0] += a * __ldg(xs + (size_t)sj * 32 + lane);
            }
        }
        __syncwarp();
    }
#pragma unroll
    for (int h = 0; h < H; h++) {
        float o = acc[h] + bv[h];
        if (ELU) o = (o > 0.f) ? o : expm1f(o);
        out[(size_t)n * HC + h * 32 + lane] = o;
    }
}

// ---------------- pooling ----------------
__global__ void pool_kernel(const int* __restrict__ batch) {
    int i = blockIdx.x * blockDim.x + threadIdx.x;
    if (i >= NN * HIDC) return;
    int n = i >> 5;
    int c = i & 31;
    int g = batch[n];
    atomicAdd(&g_sums[g * HIDC + c], g_h3[i]);
    if (c == 0) atomicAdd(&g_cnt[g], 1.f);
}

// ---------------- MLP head ----------------
__global__ void mlp_kernel(const float* __restrict__ Wm1, const float* __restrict__ bm1,
                           const float* __restrict__ Wm2, const float* __restrict__ bm2,
                           float* __restrict__ out) {
    __shared__ float emb[HIDC];
    __shared__ float hid[2 * HIDC];
    int g = blockIdx.x;
    int tid = threadIdx.x;   // 64 threads
    if (tid < HIDC) {
        float c = g_cnt[g];
        emb[tid] = g_sums[g * HIDC + tid] / fmaxf(c, 1.f);
    }
    __syncthreads();
    float a = bm1[tid];
#pragma unroll
    for (int k = 0; k < HIDC; k++) a += emb[k] * Wm1[k * (2 * HIDC) + tid];
    hid[tid] = fmaxf(a, 0.f);
    __syncthreads();
    float o = bm2[tid];
#pragma unroll
    for (int k = 0; k < 2 * HIDC; k++) o += hid[k] * Wm2[k * OUTD + tid];
    out[g * OUTD + tid] = o;
}

// ---------------- launch ----------------
extern "C" void kernel_launch(void* const* d_in, const int* in_sizes, int n_in,
                              void* d_out, int out_size) {
    const float* x         = (const float*)d_in[0];
    const int*   edge_src  = (const int*)d_in[1];
    const int*   edge_dst  = (const int*)d_in[2];
    const float* edge_attr = (const float*)d_in[3];
    const int*   batch     = (const int*)d_in[4];
    const float* W1s = (const float*)d_in[5],  *W1d = (const float*)d_in[6],  *W1e = (const float*)d_in[7];
    const float* b1s = (const float*)d_in[8],  *b1d = (const float*)d_in[9];
    const float* att1 = (const float*)d_in[10], *bias1 = (const float*)d_in[11];
    const float* W2s = (const float*)d_in[12], *W2d = (const float*)d_in[13], *W2e = (const float*)d_in[14];
    const float* b2s = (const float*)d_in[15], *b2d = (const float*)d_in[16];
    const float* att2 = (const float*)d_in[17], *bias2 = (const float*)d_in[18];
    const float* W3s = (const float*)d_in[19], *W3d = (const float*)d_in[20], *W3e = (const float*)d_in[21];
    const float* b3s = (const float*)d_in[22], *b3d = (const float*)d_in[23];
    const float* att3 = (const float*)d_in[24], *bias3 = (const float*)d_in[25];
    const float* Wm1 = (const float*)d_in[26], *bm1 = (const float*)d_in[27];
    const float* Wm2 = (const float*)d_in[28], *bm2 = (const float*)d_in[29];
    float* out = (float*)d_out;

    void *p_xs, *p_xd, *p_h1, *p_h2, *p_h3, *p_es;
    cudaGetSymbolAddress(&p_xs, g_xs);
    cudaGetSymbolAddress(&p_xd, g_xd);
    cudaGetSymbolAddress(&p_h1, g_h1);
    cudaGetSymbolAddress(&p_h2, g_h2);
    cudaGetSymbolAddress(&p_h3, g_h3);
    cudaGetSymbolAddress(&p_es, g_escore);
    float* xs = (float*)p_xs; float* xd = (float*)p_xd;
    float* h1 = (float*)p_h1; float* h2 = (float*)p_h2; float* h3 = (float*)p_h3;
    float* es = (float*)p_es;

    // CSR build (no within-bucket sort: aggregation is order-tolerant at fp level)
    zero_kernel<<<(NN + 255) / 256, 256>>>();
    hist_kernel<<<(EE + 255) / 256, 256>>>(edge_dst);
    scan1_kernel<<<SCAN_NB, SCAN_BLK>>>();
    scan2_kernel<<<1, 32>>>();
    scan3_kernel<<<(NN + 255) / 256, 256>>>();
    scatter_kernel<<<(EE + 255) / 256, 256>>>(edge_src, edge_dst);
    permute_attr_kernel<<<(EE + 255) / 256, 256>>>(edge_attr);

    const int agg_blocks = (NN * 32 + 255) / 256;

    // Layer 1: 16 -> [4,32]
    node_linear_kernel<IN_DIM, D2, 16><<<NN / 16, D2>>>(x, W1s, W1d, b1s, b1d, xs, xd);
    gat_score_kernel<HEADS, 256><<<(EE * HEADS + 255) / 256, 256>>>(xs, xd, W1e, att1, es);
    gat_aggregate_kernel<HEADS, true><<<agg_blocks, 256>>>(xs, es, bias1, h1);

    // Layer 2: 128 -> [4,32]
    node_linear_kernel<D2, D2, 16><<<NN / 16, D2>>>(h1, W2s, W2d, b2s, b2d, xs, xd);
    gat_score_kernel<HEADS, 256><<<(EE * HEADS + 255) / 256, 256>>>(xs, xd, W2e, att2, es);
    gat_aggregate_kernel<HEADS, true><<<agg_blocks, 256>>>(xs, es, bias2, h2);

    // Layer 3: 128 -> [1,32]
    node_linear_kernel<D2, HIDC, 16><<<NN / 16, HIDC>>>(h2, W3s, W3d, b3s, b3d, xs, xd);
    gat_score_kernel<1, 256><<<(EE + 255) / 256, 256>>>(xs, xd, W3e, att3, es);
    gat_aggregate_kernel<1, false><<<agg_blocks, 256>>>(xs, es, bias3, h3);

    // Pool + MLP
    pool_kernel<<<(NN * HIDC + 255) / 256, 256>>>(batch);
    mlp_kernel<<<GG, OUTD>>>(Wm1, bm1, Wm2, bm2, out);
}